// round 1
// baseline (speedup 1.0000x reference)
#include <cuda_runtime.h>
#include <cuda_bf16.h>

// SiLU(x) = x * sigmoid(x), elementwise over n fp32 values.
// n = 8*8192*2048 = 134217728, divisible by 4 -> float4 vectorization is exact.

__device__ __forceinline__ float silu1(float x) {
    // sigmoid via fast exp; rel err ~1e-6, well under 1e-3 threshold
    float s = 1.0f / (1.0f + __expf(-x));
    return x * s;
}

__global__ void __launch_bounds__(256) silu_vec4_kernel(
    const float4* __restrict__ in, float4* __restrict__ out, int n4)
{
    int i = blockIdx.x * blockDim.x + threadIdx.x;
    if (i < n4) {
        float4 v = in[i];
        float4 r;
        r.x = silu1(v.x);
        r.y = silu1(v.y);
        r.z = silu1(v.z);
        r.w = silu1(v.w);
        out[i] = r;
    }
}

// Tail kernel for n not divisible by 4 (not needed for this shape, but safe).
__global__ void silu_tail_kernel(const float* __restrict__ in,
                                 float* __restrict__ out, int start, int n)
{
    int i = start + blockIdx.x * blockDim.x + threadIdx.x;
    if (i < n) out[i] = silu1(in[i]);
}

extern "C" void kernel_launch(void* const* d_in, const int* in_sizes, int n_in,
                              void* d_out, int out_size)
{
    const float* x = (const float*)d_in[0];
    float* y = (float*)d_out;
    int n = in_sizes[0];

    int n4 = n / 4;
    if (n4 > 0) {
        int threads = 256;
        int blocks = (n4 + threads - 1) / threads;
        silu_vec4_kernel<<<blocks, threads>>>(
            (const float4*)x, (float4*)y, n4);
    }
    int rem = n - n4 * 4;
    if (rem > 0) {
        silu_tail_kernel<<<1, 256>>>(x, y, n4 * 4, n);
    }
}

// round 2
// speedup vs baseline: 1.0700x; 1.0700x over previous
#include <cuda_runtime.h>
#include <cuda_bf16.h>

// SiLU(x) = x * sigmoid(x), elementwise, n = 134217728 fp32.
// HBM-bound streaming kernel: 4 independent float4 loads per thread (MLP=4),
// non-temporal load/store hints (zero reuse), fully coalesced block tiles.

__device__ __forceinline__ float silu1(float x) {
    float s = 1.0f / (1.0f + __expf(-x));
    return x * s;
}

__device__ __forceinline__ float4 silu4(float4 v) {
    float4 r;
    r.x = silu1(v.x);
    r.y = silu1(v.y);
    r.z = silu1(v.z);
    r.w = silu1(v.w);
    return r;
}

// Each block handles a contiguous tile of 1024 float4s (16 KB elements span).
// Thread t loads offsets t, t+256, t+512, t+768 -> 4 independent in-flight
// LDG.128 per thread, all coalesced within warps.
__global__ void __launch_bounds__(256) silu_vec4x4_kernel(
    const float4* __restrict__ in, float4* __restrict__ out, int n4)
{
    int base = blockIdx.x * 1024 + threadIdx.x;

    if (base + 768 < n4) {
        // fast path: all 4 in range (true for every full tile)
        float4 v0 = __ldcs(in + base);
        float4 v1 = __ldcs(in + base + 256);
        float4 v2 = __ldcs(in + base + 512);
        float4 v3 = __ldcs(in + base + 768);
        __stcs(out + base,       silu4(v0));
        __stcs(out + base + 256, silu4(v1));
        __stcs(out + base + 512, silu4(v2));
        __stcs(out + base + 768, silu4(v3));
    } else {
        #pragma unroll
        for (int j = 0; j < 4; j++) {
            int i = base + j * 256;
            if (i < n4) __stcs(out + i, silu4(__ldcs(in + i)));
        }
    }
}

// Tail for n not divisible by 4 (not hit for this shape).
__global__ void silu_tail_kernel(const float* __restrict__ in,
                                 float* __restrict__ out, int start, int n)
{
    int i = start + blockIdx.x * blockDim.x + threadIdx.x;
    if (i < n) out[i] = silu1(in[i]);
}

extern "C" void kernel_launch(void* const* d_in, const int* in_sizes, int n_in,
                              void* d_out, int out_size)
{
    const float* x = (const float*)d_in[0];
    float* y = (float*)d_out;
    int n = in_sizes[0];

    int n4 = n / 4;
    if (n4 > 0) {
        int blocks = (n4 + 1023) / 1024;
        silu_vec4x4_kernel<<<blocks, 256>>>(
            (const float4*)x, (float4*)y, n4);
    }
    int rem = n - n4 * 4;
    if (rem > 0) {
        silu_tail_kernel<<<1, 256>>>(x, y, n4 * 4, n);
    }
}